// round 9
// baseline (speedup 1.0000x reference)
#include <cuda_runtime.h>
#include <cuda_fp16.h>
#include <cstdint>
#include <math.h>

#define B_   8
#define S_   2048
#define MD   1024
#define DK   128
#define NROWS (B_*S_)

// projected q,k,v scratch (8.39 MB each)
__device__ float g_q[NROWS*DK];
__device__ float g_k[NROWS*DK];
__device__ float g_v[NROWS*DK];

// ===================== fp16 mma + split helpers =====================
__device__ __forceinline__ void mma_f16(float c[4],
                                        uint32_t a0, uint32_t a1, uint32_t a2, uint32_t a3,
                                        uint32_t b0, uint32_t b1)
{
    asm volatile("mma.sync.aligned.m16n8k16.row.col.f32.f16.f16.f32 "
                 "{%0,%1,%2,%3}, {%4,%5,%6,%7}, {%8,%9}, {%0,%1,%2,%3};"
                 : "+f"(c[0]), "+f"(c[1]), "+f"(c[2]), "+f"(c[3])
                 : "r"(a0), "r"(a1), "r"(a2), "r"(a3), "r"(b0), "r"(b1));
}

__device__ __forceinline__ void split2h(float x0, float x1, uint32_t& hi, uint32_t& lo) {
    __half2 h = __floats2half2_rn(x0, x1);
    float2 f = __half22float2(h);
    __half2 l = __floats2half2_rn(x0 - f.x, x1 - f.y);
    hi = *reinterpret_cast<uint32_t*>(&h);
    lo = *reinterpret_cast<uint32_t*>(&l);
}

__device__ __forceinline__ uint32_t pack2h(float x0, float x1) {
    __half2 h = __floats2half2_rn(x0, x1);
    return *reinterpret_cast<uint32_t*>(&h);
}

// ===================== projection: fp16 split, 512 thr, K-stage 64 (unchanged) ====
#define PJ_S  36
#define PJ_AH 0
#define PJ_AL 4608
#define PJ_BH 9216
#define PJ_BL 13824
#define PJ_SMEM_BYTES (18432 * 4)

__global__ __launch_bounds__(512) void proj_mma(
    const float* __restrict__ Xq, const float* __restrict__ Xk, const float* __restrict__ Xv,
    const float* __restrict__ Wq, const float* __restrict__ Wk, const float* __restrict__ Wv)
{
    const float* X; const float* W; float* Y;
    if (blockIdx.y == 0)      { X = Xq; W = Wq; Y = g_q; }
    else if (blockIdx.y == 1) { X = Xk; W = Wk; Y = g_k; }
    else                      { X = Xv; W = Wv; Y = g_v; }

    extern __shared__ uint32_t su[];

    const int tid  = threadIdx.x;
    const int wid  = tid >> 5, lane = tid & 31;
    const int wr   = wid >> 2, wc = wid & 3;
    const int rowt = lane >> 2;
    const int colt = lane & 3;
    const int row0 = blockIdx.x * 128;

    float acc[2][4][4];
    #pragma unroll
    for (int mt = 0; mt < 2; mt++)
        #pragma unroll
        for (int nt = 0; nt < 4; nt++)
            #pragma unroll
            for (int i = 0; i < 4; i++) acc[mt][nt][i] = 0.f;

    #pragma unroll 1
    for (int k0 = 0; k0 < MD; k0 += 64) {
        #pragma unroll
        for (int t = 0; t < 4; t++) {
            int idx = tid + t * 512;
            int row = idx >> 4, f4 = idx & 15;
            float4 a = *(const float4*)(X + (size_t)(row0 + row) * MD + k0 + f4 * 4);
            uint32_t h0, l0, h1, l1;
            split2h(a.x, a.y, h0, l0);
            split2h(a.z, a.w, h1, l1);
            *(uint2*)&su[PJ_AH + row * PJ_S + f4 * 2] = make_uint2(h0, h1);
            *(uint2*)&su[PJ_AL + row * PJ_S + f4 * 2] = make_uint2(l0, l1);

            float4 b = *(const float4*)(W + (size_t)row * MD + k0 + f4 * 4);
            split2h(b.x, b.y, h0, l0);
            split2h(b.z, b.w, h1, l1);
            *(uint2*)&su[PJ_BH + row * PJ_S + f4 * 2] = make_uint2(h0, h1);
            *(uint2*)&su[PJ_BL + row * PJ_S + f4 * 2] = make_uint2(l0, l1);
        }
        __syncthreads();

        #pragma unroll
        for (int c = 0; c < 4; c++) {
            const int co = c * 8;
            uint32_t ah[2][4], al[2][4];
            #pragma unroll
            for (int mt = 0; mt < 2; mt++) {
                int o0 = (wr * 32 + mt * 16 + rowt) * PJ_S + co + colt;
                int o1 = o0 + 8 * PJ_S;
                ah[mt][0] = su[PJ_AH + o0];      ah[mt][1] = su[PJ_AH + o1];
                ah[mt][2] = su[PJ_AH + o0 + 4];  ah[mt][3] = su[PJ_AH + o1 + 4];
                al[mt][0] = su[PJ_AL + o0];      al[mt][1] = su[PJ_AL + o1];
                al[mt][2] = su[PJ_AL + o0 + 4];  al[mt][3] = su[PJ_AL + o1 + 4];
            }
            #pragma unroll
            for (int nt = 0; nt < 4; nt++) {
                int ob = (wc * 32 + nt * 8 + rowt) * PJ_S + co + colt;
                uint32_t bh0 = su[PJ_BH + ob], bh1 = su[PJ_BH + ob + 4];
                uint32_t bl0 = su[PJ_BL + ob], bl1 = su[PJ_BL + ob + 4];
                #pragma unroll
                for (int mt = 0; mt < 2; mt++) {
                    mma_f16(acc[mt][nt], ah[mt][0], ah[mt][1], ah[mt][2], ah[mt][3], bh0, bh1);
                    mma_f16(acc[mt][nt], ah[mt][0], ah[mt][1], ah[mt][2], ah[mt][3], bl0, bl1);
                    mma_f16(acc[mt][nt], al[mt][0], al[mt][1], al[mt][2], al[mt][3], bh0, bh1);
                }
            }
        }
        __syncthreads();
    }

    #pragma unroll
    for (int mt = 0; mt < 2; mt++) {
        int gr = row0 + wr * 32 + mt * 16 + rowt;
        #pragma unroll
        for (int nt = 0; nt < 4; nt++) {
            int gc = wc * 32 + nt * 8 + colt * 2;
            float2 c01 = { acc[mt][nt][0], acc[mt][nt][1] };
            float2 c23 = { acc[mt][nt][2], acc[mt][nt][3] };
            *(float2*)(Y + (size_t)gr * DK + gc)       = c01;
            *(float2*)(Y + (size_t)(gr + 8) * DK + gc) = c23;
        }
    }
}

// ===================== fp16 flash attention, BQ=64, 256 thr, 2 CTAs/SM ============
// 8 warps (2x4), warp tile 32x32.
// QK = Qh*Kh + Qh*Kl (Q residual dropped).  PV = Ph*Vh + Ph*Vl.
// smem 106,496 B/CTA -> 2 CTAs resident per SM for cross-CTA phase overlap.

#define AQ_S  68
#define AV_S  136
#define U_Q   0                       // Qh only: 64*68            = 4352 u32
#define U_KV  4352                    // Kh/Vh @+0, Kl/Vl @+8704   = 17408 u32
#define U_P   21760                   // Ph only: 64*68            = 4352 u32
#define U_RM  26112                   // redmax: 64 rows x 4
#define U_RS  26368                   // redsum: 64 rows x 4
#define A_SMEM_BYTES ((26624) * 4)    // 106,496 B

__global__ __launch_bounds__(256, 2) void attn_tc(const int* __restrict__ mask,
                                                  float* __restrict__ out)
{
    extern __shared__ uint32_t su[];
    float* redm = (float*)&su[U_RM];
    float* reds = (float*)&su[U_RS];

    const int tid = threadIdx.x;
    const int wid = tid >> 5, lane = tid & 31;
    const int wr = wid >> 2, wc = wid & 3;         // 2x4 warp grid
    const int rowt = lane >> 2, colt = lane & 3;
    const int qt = blockIdx.x, b = blockIdx.y;

    const float4* Qg = (const float4*)(g_q + ((size_t)b * S_ + (size_t)qt * 64) * DK);
    const float4* Kg = (const float4*)(g_k + (size_t)b * S_ * DK);
    const float4* Vg = (const float4*)(g_v + (size_t)b * S_ * DK);

    // ---- stage Q (hi only) ----
    #pragma unroll
    for (int t = 0; t < 8; t++) {
        int idx = tid + t * 256;                   // 0..2047 float4
        int row = idx >> 5, f4 = idx & 31;
        float4 q = Qg[idx];
        *(uint2*)&su[U_Q + row * AQ_S + f4 * 2] =
            make_uint2(pack2h(q.x, q.y), pack2h(q.z, q.w));
    }

    float acc[2][4][4];
    #pragma unroll
    for (int mt = 0; mt < 2; mt++)
        #pragma unroll
        for (int nt = 0; nt < 4; nt++)
            #pragma unroll
            for (int i = 0; i < 4; i++) acc[mt][nt][i] = 0.f;

    float mrow[4] = {-1e30f, -1e30f, -1e30f, -1e30f};
    float lrow[4] = {0.f, 0.f, 0.f, 0.f};
    const float scale = 0.08838834764831845f;

    #pragma unroll 1
    for (int kt = 0; kt < S_ / 128; kt++) {
        __syncthreads();
        // ---- stage K packed hi/lo ----
        const float4* Ksrc = Kg + (size_t)kt * 128 * 32;
        #pragma unroll
        for (int t = 0; t < 16; t++) {
            int idx = tid + t * 256;               // 0..4095
            int row = idx >> 5, f4 = idx & 31;
            float4 k = Ksrc[idx];
            uint32_t h0, l0, h1, l1;
            split2h(k.x, k.y, h0, l0);
            split2h(k.z, k.w, h1, l1);
            *(uint2*)&su[U_KV + row * AQ_S + f4 * 2]        = make_uint2(h0, h1);
            *(uint2*)&su[U_KV + 8704 + row * AQ_S + f4 * 2] = make_uint2(l0, l1);
        }
        __syncthreads();

        // ---- S = Qh*(Kh + Kl) ----
        float s[2][4][4];
        #pragma unroll
        for (int mt = 0; mt < 2; mt++)
            #pragma unroll
            for (int nt = 0; nt < 4; nt++)
                #pragma unroll
                for (int i = 0; i < 4; i++) s[mt][nt][i] = 0.f;

        #pragma unroll 1
        for (int c = 0; c < 8; c++) {
            const int co = c * 8;
            uint32_t ah[2][4];
            #pragma unroll
            for (int mt = 0; mt < 2; mt++) {
                int o0 = (wr * 32 + mt * 16 + rowt) * AQ_S + co + colt;
                int o1 = o0 + 8 * AQ_S;
                ah[mt][0] = su[U_Q + o0];      ah[mt][1] = su[U_Q + o1];
                ah[mt][2] = su[U_Q + o0 + 4];  ah[mt][3] = su[U_Q + o1 + 4];
            }
            #pragma unroll
            for (int nt = 0; nt < 4; nt++) {
                int ob = (wc * 32 + nt * 8 + rowt) * AQ_S + co + colt;
                uint32_t bh0 = su[U_KV + ob], bh1 = su[U_KV + ob + 4];
                uint32_t bl0 = su[U_KV + 8704 + ob], bl1 = su[U_KV + 8704 + ob + 4];
                #pragma unroll
                for (int mt = 0; mt < 2; mt++) {
                    mma_f16(s[mt][nt], ah[mt][0], ah[mt][1], ah[mt][2], ah[mt][3], bh0, bh1);
                    mma_f16(s[mt][nt], ah[mt][0], ah[mt][1], ah[mt][2], ah[mt][3], bl0, bl1);
                }
            }
        }

        // ---- mask + scale; per-warp partial row max ----
        const int* mbase = mask + ((size_t)b * S_ + (size_t)qt * 64) * S_ + (size_t)kt * 128
                                + wc * 32 + colt * 2;
        #pragma unroll
        for (int mt = 0; mt < 2; mt++) {
            int r0 = wr * 32 + mt * 16 + rowt;
            const int* m0p = mbase + (size_t)r0 * S_;
            const int* m1p = mbase + (size_t)(r0 + 8) * S_;
            float mx0 = -1e30f, mx1 = -1e30f;
            #pragma unroll
            for (int nt = 0; nt < 4; nt++) {
                int2 ma = *(const int2*)(m0p + nt * 8);
                int2 mb = *(const int2*)(m1p + nt * 8);
                s[mt][nt][0] = ma.x ? s[mt][nt][0] * scale : -1e9f;
                s[mt][nt][1] = ma.y ? s[mt][nt][1] * scale : -1e9f;
                s[mt][nt][2] = mb.x ? s[mt][nt][2] * scale : -1e9f;
                s[mt][nt][3] = mb.y ? s[mt][nt][3] * scale : -1e9f;
                mx0 = fmaxf(mx0, fmaxf(s[mt][nt][0], s[mt][nt][1]));
                mx1 = fmaxf(mx1, fmaxf(s[mt][nt][2], s[mt][nt][3]));
            }
            mx0 = fmaxf(mx0, __shfl_xor_sync(0xffffffffu, mx0, 1));
            mx0 = fmaxf(mx0, __shfl_xor_sync(0xffffffffu, mx0, 2));
            mx1 = fmaxf(mx1, __shfl_xor_sync(0xffffffffu, mx1, 1));
            mx1 = fmaxf(mx1, __shfl_xor_sync(0xffffffffu, mx1, 2));
            if (colt == 0) {
                redm[r0 * 4 + wc]       = mx0;
                redm[(r0 + 8) * 4 + wc] = mx1;
            }
        }
        __syncthreads();

        // ---- stage V packed-along-k hi/lo (over K buffer) ----
        const float4* Vsrc = Vg + (size_t)kt * 128 * 32;
        #pragma unroll
        for (int t = 0; t < 8; t++) {
            int idx = tid + t * 256;               // 0..2047
            int kp = idx >> 5, n4 = idx & 31;
            float4 va = Vsrc[(size_t)(2 * kp) * 32 + n4];
            float4 vb = Vsrc[(size_t)(2 * kp + 1) * 32 + n4];
            uint32_t h[4], l[4];
            split2h(va.x, vb.x, h[0], l[0]);
            split2h(va.y, vb.y, h[1], l[1]);
            split2h(va.z, vb.z, h[2], l[2]);
            split2h(va.w, vb.w, h[3], l[3]);
            *(uint4*)&su[U_KV + kp * AV_S + n4 * 4]        = make_uint4(h[0], h[1], h[2], h[3]);
            *(uint4*)&su[U_KV + 8704 + kp * AV_S + n4 * 4] = make_uint4(l[0], l[1], l[2], l[3]);
        }

        // ---- softmax: exp, partial sums, rescale acc, write Ph ----
        float crr[4];
        #pragma unroll
        for (int mt = 0; mt < 2; mt++) {
            int r0 = wr * 32 + mt * 16 + rowt;
            int r1 = r0 + 8;
            float mn0 = fmaxf(fmaxf(redm[r0 * 4], redm[r0 * 4 + 1]),
                              fmaxf(redm[r0 * 4 + 2], redm[r0 * 4 + 3]));
            float mn1 = fmaxf(fmaxf(redm[r1 * 4], redm[r1 * 4 + 1]),
                              fmaxf(redm[r1 * 4 + 2], redm[r1 * 4 + 3]));
            mn0 = fmaxf(mrow[mt*2], mn0);
            mn1 = fmaxf(mrow[mt*2+1], mn1);
            crr[mt*2]   = __expf(mrow[mt*2]   - mn0);
            crr[mt*2+1] = __expf(mrow[mt*2+1] - mn1);
            mrow[mt*2] = mn0;  mrow[mt*2+1] = mn1;
            float sm0 = 0.f, sm1 = 0.f;
            #pragma unroll
            for (int nt = 0; nt < 4; nt++) {
                float p0 = __expf(s[mt][nt][0] - mn0);
                float p1 = __expf(s[mt][nt][1] - mn0);
                float p2 = __expf(s[mt][nt][2] - mn1);
                float p3 = __expf(s[mt][nt][3] - mn1);
                sm0 += p0 + p1;  sm1 += p2 + p3;
                int pc = wc * 16 + nt * 4 + colt;
                su[U_P + r0 * AQ_S + pc] = pack2h(p0, p1);
                su[U_P + r1 * AQ_S + pc] = pack2h(p2, p3);
                acc[mt][nt][0] *= crr[mt*2];   acc[mt][nt][1] *= crr[mt*2];
                acc[mt][nt][2] *= crr[mt*2+1]; acc[mt][nt][3] *= crr[mt*2+1];
            }
            sm0 += __shfl_xor_sync(0xffffffffu, sm0, 1);
            sm0 += __shfl_xor_sync(0xffffffffu, sm0, 2);
            sm1 += __shfl_xor_sync(0xffffffffu, sm1, 1);
            sm1 += __shfl_xor_sync(0xffffffffu, sm1, 2);
            if (colt == 0) {
                reds[r0 * 4 + wc] = sm0;
                reds[r1 * 4 + wc] = sm1;
            }
        }
        __syncthreads();

        // ---- update l ----
        #pragma unroll
        for (int mt = 0; mt < 2; mt++) {
            int r0 = wr * 32 + mt * 16 + rowt;
            int r1 = r0 + 8;
            lrow[mt*2]   = lrow[mt*2]   * crr[mt*2]
                         + reds[r0*4] + reds[r0*4+1] + reds[r0*4+2] + reds[r0*4+3];
            lrow[mt*2+1] = lrow[mt*2+1] * crr[mt*2+1]
                         + reds[r1*4] + reds[r1*4+1] + reds[r1*4+2] + reds[r1*4+3];
        }

        // ---- acc += Ph * (Vh + Vl) ----
        #pragma unroll 1
        for (int c = 0; c < 8; c++) {
            const int co = c * 8;
            uint32_t ah[2][4];
            #pragma unroll
            for (int mt = 0; mt < 2; mt++) {
                int o0 = (wr * 32 + mt * 16 + rowt) * AQ_S + co + colt;
                int o1 = o0 + 8 * AQ_S;
                ah[mt][0] = su[U_P + o0];      ah[mt][1] = su[U_P + o1];
                ah[mt][2] = su[U_P + o0 + 4];  ah[mt][3] = su[U_P + o1 + 4];
            }
            #pragma unroll
            for (int nt = 0; nt < 4; nt++) {
                int ob = (co + colt) * AV_S + wc * 32 + nt * 8 + rowt;
                uint32_t bh0 = su[U_KV + ob], bh1 = su[U_KV + ob + 4 * AV_S];
                uint32_t bl0 = su[U_KV + 8704 + ob], bl1 = su[U_KV + 8704 + ob + 4 * AV_S];
                #pragma unroll
                for (int mt = 0; mt < 2; mt++) {
                    mma_f16(acc[mt][nt], ah[mt][0], ah[mt][1], ah[mt][2], ah[mt][3], bh0, bh1);
                    mma_f16(acc[mt][nt], ah[mt][0], ah[mt][1], ah[mt][2], ah[mt][3], bl0, bl1);
                }
            }
        }
    }

    // ---- epilogue ----
    #pragma unroll
    for (int mt = 0; mt < 2; mt++) {
        int r0 = wr * 32 + mt * 16 + rowt;
        float il0 = 1.f / lrow[mt*2];
        float il1 = 1.f / lrow[mt*2+1];
        size_t gr = (size_t)b * S_ + (size_t)qt * 64 + r0;
        #pragma unroll
        for (int nt = 0; nt < 4; nt++) {
            int c0 = wc * 32 + nt * 8 + colt * 2;
            float2 o0 = { acc[mt][nt][0] * il0, acc[mt][nt][1] * il0 };
            float2 o1 = { acc[mt][nt][2] * il1, acc[mt][nt][3] * il1 };
            *(float2*)(out + gr * DK + c0)       = o0;
            *(float2*)(out + (gr + 8) * DK + c0) = o1;
        }
    }
}

// ===================== launch =====================
extern "C" void kernel_launch(void* const* d_in, const int* in_sizes, int n_in,
                              void* d_out, int out_size)
{
    const float* query = (const float*)d_in[0];
    const float* key   = (const float*)d_in[1];
    const float* value = (const float*)d_in[2];
    const int*   maskp = (const int*)  d_in[3];
    const float* Wq    = (const float*)d_in[4];
    const float* Wk    = (const float*)d_in[5];
    const float* Wv    = (const float*)d_in[6];
    float* out = (float*)d_out;

    cudaFuncSetAttribute(proj_mma, cudaFuncAttributeMaxDynamicSharedMemorySize,
                         (int)PJ_SMEM_BYTES);
    cudaFuncSetAttribute(attn_tc, cudaFuncAttributeMaxDynamicSharedMemorySize,
                         (int)A_SMEM_BYTES);

    proj_mma<<<dim3(NROWS / 128, 3), 512, PJ_SMEM_BYTES>>>(query, key, value, Wq, Wk, Wv);
    attn_tc<<<dim3(S_ / 64, B_), 256, A_SMEM_BYTES>>>(maskp, out);
}

// round 10
// speedup vs baseline: 1.0740x; 1.0740x over previous
#include <cuda_runtime.h>
#include <cuda_fp16.h>
#include <cstdint>
#include <math.h>

#define B_   8
#define S_   2048
#define MD   1024
#define DK   128
#define NROWS (B_*S_)

// pre-split half2-packed projections (u32 = half2 along dk), 4.19 MB each
__device__ uint32_t g_qh[NROWS*64];
__device__ uint32_t g_kh[NROWS*64];
__device__ uint32_t g_kl[NROWS*64];
__device__ uint32_t g_vh[NROWS*64];
__device__ uint32_t g_vl[NROWS*64];
// pre-split weights: [3][128][512] u32 (half2 along k)
__device__ uint32_t g_wh[3*128*512];
__device__ uint32_t g_wl[3*128*512];

// ===================== fp16 mma + split helpers =====================
__device__ __forceinline__ void mma_f16(float c[4],
                                        uint32_t a0, uint32_t a1, uint32_t a2, uint32_t a3,
                                        uint32_t b0, uint32_t b1)
{
    asm volatile("mma.sync.aligned.m16n8k16.row.col.f32.f16.f16.f32 "
                 "{%0,%1,%2,%3}, {%4,%5,%6,%7}, {%8,%9}, {%0,%1,%2,%3};"
                 : "+f"(c[0]), "+f"(c[1]), "+f"(c[2]), "+f"(c[3])
                 : "r"(a0), "r"(a1), "r"(a2), "r"(a3), "r"(b0), "r"(b1));
}

__device__ __forceinline__ void split2h(float x0, float x1, uint32_t& hi, uint32_t& lo) {
    __half2 h = __floats2half2_rn(x0, x1);
    float2 f = __half22float2(h);
    __half2 l = __floats2half2_rn(x0 - f.x, x1 - f.y);
    hi = *reinterpret_cast<uint32_t*>(&h);
    lo = *reinterpret_cast<uint32_t*>(&l);
}

__device__ __forceinline__ uint32_t pack2h(float x0, float x1) {
    __half2 h = __floats2half2_rn(x0, x1);
    return *reinterpret_cast<uint32_t*>(&h);
}

// ===================== W pre-split kernel =====================
__global__ __launch_bounds__(256) void presplit_w(
    const float* __restrict__ Wq, const float* __restrict__ Wk, const float* __restrict__ Wv)
{
    int idx = blockIdx.x * 256 + threadIdx.x;       // 0 .. 3*128*512-1
    int w = idx >> 16;                               // /65536
    int rem = idx & 65535;
    const float* W = (w == 0) ? Wq : (w == 1) ? Wk : Wv;
    float2 v = *(const float2*)(W + rem * 2);
    uint32_t h, l;
    split2h(v.x, v.y, h, l);
    g_wh[idx] = h;
    g_wl[idx] = l;
}

// ===================== projection: fp16 split, 512 thr, K-stage 64 ================
#define PJ_S  36
#define PJ_AH 0
#define PJ_AL 4608
#define PJ_BH 9216
#define PJ_BL 13824
#define PJ_SMEM_BYTES (18432 * 4)

__global__ __launch_bounds__(512) void proj_mma(
    const float* __restrict__ Xq, const float* __restrict__ Xk, const float* __restrict__ Xv)
{
    const int kind = blockIdx.y;                    // 0=Q 1=K 2=V
    const float* X = (kind == 0) ? Xq : (kind == 1) ? Xk : Xv;

    extern __shared__ uint32_t su[];

    const int tid  = threadIdx.x;
    const int wid  = tid >> 5, lane = tid & 31;
    const int wr   = wid >> 2, wc = wid & 3;
    const int rowt = lane >> 2;
    const int colt = lane & 3;
    const int row0 = blockIdx.x * 128;
    const uint4* Wh4 = (const uint4*)(g_wh + kind * 65536);
    const uint4* Wl4 = (const uint4*)(g_wl + kind * 65536);

    float acc[2][4][4];
    #pragma unroll
    for (int mt = 0; mt < 2; mt++)
        #pragma unroll
        for (int nt = 0; nt < 4; nt++)
            #pragma unroll
            for (int i = 0; i < 4; i++) acc[mt][nt][i] = 0.f;

    #pragma unroll 1
    for (int k0 = 0; k0 < MD; k0 += 64) {
        // ---- stage A (split X in regs) ----
        #pragma unroll
        for (int t = 0; t < 4; t++) {
            int idx = tid + t * 512;                // 0..2047 float4
            int row = idx >> 4, f4 = idx & 15;
            float4 a = *(const float4*)(X + (size_t)(row0 + row) * MD + k0 + f4 * 4);
            uint32_t h0, l0, h1, l1;
            split2h(a.x, a.y, h0, l0);
            split2h(a.z, a.w, h1, l1);
            *(uint2*)&su[PJ_AH + row * PJ_S + f4 * 2] = make_uint2(h0, h1);
            *(uint2*)&su[PJ_AL + row * PJ_S + f4 * 2] = make_uint2(l0, l1);
        }
        // ---- stage B (pure copy of pre-split W) ----
        #pragma unroll
        for (int t = 0; t < 2; t++) {
            int idx = tid + t * 512;                // 0..1023 uint4
            int row = idx >> 3, c4 = idx & 7;
            int g = row * 128 + (k0 >> 3) + c4;     // uint4 index into 512-u32 rows
            *(uint4*)&su[PJ_BH + row * PJ_S + c4 * 4] = Wh4[g];
            *(uint4*)&su[PJ_BL + row * PJ_S + c4 * 4] = Wl4[g];
        }
        __syncthreads();

        #pragma unroll
        for (int c = 0; c < 4; c++) {
            const int co = c * 8;
            uint32_t ah[2][4], al[2][4];
            #pragma unroll
            for (int mt = 0; mt < 2; mt++) {
                int o0 = (wr * 32 + mt * 16 + rowt) * PJ_S + co + colt;
                int o1 = o0 + 8 * PJ_S;
                ah[mt][0] = su[PJ_AH + o0];      ah[mt][1] = su[PJ_AH + o1];
                ah[mt][2] = su[PJ_AH + o0 + 4];  ah[mt][3] = su[PJ_AH + o1 + 4];
                al[mt][0] = su[PJ_AL + o0];      al[mt][1] = su[PJ_AL + o1];
                al[mt][2] = su[PJ_AL + o0 + 4];  al[mt][3] = su[PJ_AL + o1 + 4];
            }
            #pragma unroll
            for (int nt = 0; nt < 4; nt++) {
                int ob = (wc * 32 + nt * 8 + rowt) * PJ_S + co + colt;
                uint32_t bh0 = su[PJ_BH + ob], bh1 = su[PJ_BH + ob + 4];
                uint32_t bl0 = su[PJ_BL + ob], bl1 = su[PJ_BL + ob + 4];
                #pragma unroll
                for (int mt = 0; mt < 2; mt++) {
                    mma_f16(acc[mt][nt], ah[mt][0], ah[mt][1], ah[mt][2], ah[mt][3], bh0, bh1);
                    mma_f16(acc[mt][nt], ah[mt][0], ah[mt][1], ah[mt][2], ah[mt][3], bl0, bl1);
                    mma_f16(acc[mt][nt], al[mt][0], al[mt][1], al[mt][2], al[mt][3], bh0, bh1);
                }
            }
        }
        __syncthreads();
    }

    // ---- epilogue: write pre-split half2 directly ----
    #pragma unroll
    for (int mt = 0; mt < 2; mt++) {
        int gr = row0 + wr * 32 + mt * 16 + rowt;
        #pragma unroll
        for (int nt = 0; nt < 4; nt++) {
            int gc = wc * 32 + nt * 8 + colt * 2;
            int o0 = gr * 64 + (gc >> 1);
            int o1 = (gr + 8) * 64 + (gc >> 1);
            if (kind == 0) {
                g_qh[o0] = pack2h(acc[mt][nt][0], acc[mt][nt][1]);
                g_qh[o1] = pack2h(acc[mt][nt][2], acc[mt][nt][3]);
            } else {
                uint32_t h, l;
                uint32_t* GH = (kind == 1) ? g_kh : g_vh;
                uint32_t* GL = (kind == 1) ? g_kl : g_vl;
                split2h(acc[mt][nt][0], acc[mt][nt][1], h, l);
                GH[o0] = h;  GL[o0] = l;
                split2h(acc[mt][nt][2], acc[mt][nt][3], h, l);
                GH[o1] = h;  GL[o1] = l;
            }
        }
    }
}

// ===================== fp16 flash attention, BQ=128, 512 thr ======================
// 16 warps (4x4), warp tile 32x32.  QK = Qh*(Kh+Kl).  PV = Ph*(Vh+Vl).
// All operands pre-split in global; staging is pure copy (+PRMT transpose for V).

#define AQ_S  68
#define AV_S  136
#define U_Q   0                       // Qh: 128*68 = 8704 u32
#define U_KV  8704                    // Kh/Vh @+0, Kl/Vl @+8704
#define U_P   26112                   // Ph: 8704
#define U_RM  34816                   // redmax: 128 x 4
#define U_RS  35328                   // redsum: 128 x 4
#define A_SMEM_BYTES ((35840) * 4)    // 143,360 B

__global__ __launch_bounds__(512) void attn_tc(const int* __restrict__ mask,
                                               float* __restrict__ out)
{
    extern __shared__ uint32_t su[];
    float* redm = (float*)&su[U_RM];
    float* reds = (float*)&su[U_RS];

    const int tid = threadIdx.x;
    const int wid = tid >> 5, lane = tid & 31;
    const int wr = wid >> 2, wc = wid & 3;
    const int rowt = lane >> 2, colt = lane & 3;
    const int qt = blockIdx.x, b = blockIdx.y;

    const uint4* Qg = (const uint4*)(g_qh + ((size_t)b * S_ + (size_t)qt * 128) * 64);

    // ---- stage Q (copy) ----
    #pragma unroll
    for (int t = 0; t < 4; t++) {
        int idx = tid + t * 512;                   // 0..2047 uint4
        int row = idx >> 4, c4 = idx & 15;
        *(uint4*)&su[U_Q + row * AQ_S + c4 * 4] = Qg[idx];
    }

    float acc[2][4][4];
    #pragma unroll
    for (int mt = 0; mt < 2; mt++)
        #pragma unroll
        for (int nt = 0; nt < 4; nt++)
            #pragma unroll
            for (int i = 0; i < 4; i++) acc[mt][nt][i] = 0.f;

    float mrow[4] = {-1e30f, -1e30f, -1e30f, -1e30f};
    float lrow[4] = {0.f, 0.f, 0.f, 0.f};
    const float scale = 0.08838834764831845f;

    #pragma unroll 1
    for (int kt = 0; kt < S_ / 128; kt++) {
        __syncthreads();
        // ---- stage K (copy hi+lo) ----
        const uint4* Khg = (const uint4*)(g_kh + ((size_t)b * S_ + (size_t)kt * 128) * 64);
        const uint4* Klg = (const uint4*)(g_kl + ((size_t)b * S_ + (size_t)kt * 128) * 64);
        #pragma unroll
        for (int t = 0; t < 4; t++) {
            int idx = tid + t * 512;
            int row = idx >> 4, c4 = idx & 15;
            *(uint4*)&su[U_KV + row * AQ_S + c4 * 4]        = Khg[idx];
            *(uint4*)&su[U_KV + 8704 + row * AQ_S + c4 * 4] = Klg[idx];
        }
        __syncthreads();

        // ---- S = Qh*(Kh+Kl) ----
        float s[2][4][4];
        #pragma unroll
        for (int mt = 0; mt < 2; mt++)
            #pragma unroll
            for (int nt = 0; nt < 4; nt++)
                #pragma unroll
                for (int i = 0; i < 4; i++) s[mt][nt][i] = 0.f;

        #pragma unroll 1
        for (int c = 0; c < 8; c++) {
            const int co = c * 8;
            uint32_t ah[2][4];
            #pragma unroll
            for (int mt = 0; mt < 2; mt++) {
                int o0 = (wr * 32 + mt * 16 + rowt) * AQ_S + co + colt;
                int o1 = o0 + 8 * AQ_S;
                ah[mt][0] = su[U_Q + o0];      ah[mt][1] = su[U_Q + o1];
                ah[mt][2] = su[U_Q + o0 + 4];  ah[mt][3] = su[U_Q + o1 + 4];
            }
            #pragma unroll
            for (int nt = 0; nt < 4; nt++) {
                int ob = (wc * 32 + nt * 8 + rowt) * AQ_S + co + colt;
                uint32_t bh0 = su[U_KV + ob], bh1 = su[U_KV + ob + 4];
                uint32_t bl0 = su[U_KV + 8704 + ob], bl1 = su[U_KV + 8704 + ob + 4];
                #pragma unroll
                for (int mt = 0; mt < 2; mt++) {
                    mma_f16(s[mt][nt], ah[mt][0], ah[mt][1], ah[mt][2], ah[mt][3], bh0, bh1);
                    mma_f16(s[mt][nt], ah[mt][0], ah[mt][1], ah[mt][2], ah[mt][3], bl0, bl1);
                }
            }
        }

        // ---- mask + scale; per-warp partial row max ----
        const int* mbase = mask + ((size_t)b * S_ + (size_t)qt * 128) * S_ + (size_t)kt * 128
                                + wc * 32 + colt * 2;
        #pragma unroll
        for (int mt = 0; mt < 2; mt++) {
            int r0 = wr * 32 + mt * 16 + rowt;
            const int* m0p = mbase + (size_t)r0 * S_;
            const int* m1p = mbase + (size_t)(r0 + 8) * S_;
            float mx0 = -1e30f, mx1 = -1e30f;
            #pragma unroll
            for (int nt = 0; nt < 4; nt++) {
                int2 ma = *(const int2*)(m0p + nt * 8);
                int2 mb = *(const int2*)(m1p + nt * 8);
                s[mt][nt][0] = ma.x ? s[mt][nt][0] * scale : -1e9f;
                s[mt][nt][1] = ma.y ? s[mt][nt][1] * scale : -1e9f;
                s[mt][nt][2] = mb.x ? s[mt][nt][2] * scale : -1e9f;
                s[mt][nt][3] = mb.y ? s[mt][nt][3] * scale : -1e9f;
                mx0 = fmaxf(mx0, fmaxf(s[mt][nt][0], s[mt][nt][1]));
                mx1 = fmaxf(mx1, fmaxf(s[mt][nt][2], s[mt][nt][3]));
            }
            mx0 = fmaxf(mx0, __shfl_xor_sync(0xffffffffu, mx0, 1));
            mx0 = fmaxf(mx0, __shfl_xor_sync(0xffffffffu, mx0, 2));
            mx1 = fmaxf(mx1, __shfl_xor_sync(0xffffffffu, mx1, 1));
            mx1 = fmaxf(mx1, __shfl_xor_sync(0xffffffffu, mx1, 2));
            if (colt == 0) {
                redm[r0 * 4 + wc]       = mx0;
                redm[(r0 + 8) * 4 + wc] = mx1;
            }
        }
        __syncthreads();

        // ---- stage V: transpose-pack pre-split halves (PRMT) ----
        const uint32_t* Vhg = g_vh + ((size_t)b * S_ + (size_t)kt * 128) * 64;
        const uint32_t* Vlg = g_vl + ((size_t)b * S_ + (size_t)kt * 128) * 64;
        #pragma unroll
        for (int t = 0; t < 4; t++) {
            int idx = tid + t * 512;               // 0..2047
            int kp = idx >> 5, n4 = idx & 31;
            int ga = (2 * kp) * 64 + n4 * 2;
            int gb = ga + 64;
            uint2 ah2 = *(const uint2*)(Vhg + ga);
            uint2 bh2 = *(const uint2*)(Vhg + gb);
            uint4 oh;
            oh.x = __byte_perm(ah2.x, bh2.x, 0x5410);
            oh.y = __byte_perm(ah2.x, bh2.x, 0x7632);
            oh.z = __byte_perm(ah2.y, bh2.y, 0x5410);
            oh.w = __byte_perm(ah2.y, bh2.y, 0x7632);
            *(uint4*)&su[U_KV + kp * AV_S + n4 * 4] = oh;
            uint2 al2 = *(const uint2*)(Vlg + ga);
            uint2 bl2 = *(const uint2*)(Vlg + gb);
            uint4 ol;
            ol.x = __byte_perm(al2.x, bl2.x, 0x5410);
            ol.y = __byte_perm(al2.x, bl2.x, 0x7632);
            ol.z = __byte_perm(al2.y, bl2.y, 0x5410);
            ol.w = __byte_perm(al2.y, bl2.y, 0x7632);
            *(uint4*)&su[U_KV + 8704 + kp * AV_S + n4 * 4] = ol;
        }

        // ---- softmax: exp, partial sums, rescale acc, write Ph ----
        float crr[4];
        #pragma unroll
        for (int mt = 0; mt < 2; mt++) {
            int r0 = wr * 32 + mt * 16 + rowt;
            int r1 = r0 + 8;
            float mn0 = fmaxf(fmaxf(redm[r0 * 4], redm[r0 * 4 + 1]),
                              fmaxf(redm[r0 * 4 + 2], redm[r0 * 4 + 3]));
            float mn1 = fmaxf(fmaxf(redm[r1 * 4], redm[r1 * 4 + 1]),
                              fmaxf(redm[r1 * 4 + 2], redm[r1 * 4 + 3]));
            mn0 = fmaxf(mrow[mt*2], mn0);
            mn1 = fmaxf(mrow[mt*2+1], mn1);
            crr[mt*2]   = __expf(mrow[mt*2]   - mn0);
            crr[mt*2+1] = __expf(mrow[mt*2+1] - mn1);
            mrow[mt*2] = mn0;  mrow[mt*2+1] = mn1;
            float sm0 = 0.f, sm1 = 0.f;
            #pragma unroll
            for (int nt = 0; nt < 4; nt++) {
                float p0 = __expf(s[mt][nt][0] - mn0);
                float p1 = __expf(s[mt][nt][1] - mn0);
                float p2 = __expf(s[mt][nt][2] - mn1);
                float p3 = __expf(s[mt][nt][3] - mn1);
                sm0 += p0 + p1;  sm1 += p2 + p3;
                int pc = wc * 16 + nt * 4 + colt;
                su[U_P + r0 * AQ_S + pc] = pack2h(p0, p1);
                su[U_P + r1 * AQ_S + pc] = pack2h(p2, p3);
                acc[mt][nt][0] *= crr[mt*2];   acc[mt][nt][1] *= crr[mt*2];
                acc[mt][nt][2] *= crr[mt*2+1]; acc[mt][nt][3] *= crr[mt*2+1];
            }
            sm0 += __shfl_xor_sync(0xffffffffu, sm0, 1);
            sm0 += __shfl_xor_sync(0xffffffffu, sm0, 2);
            sm1 += __shfl_xor_sync(0xffffffffu, sm1, 1);
            sm1 += __shfl_xor_sync(0xffffffffu, sm1, 2);
            if (colt == 0) {
                reds[r0 * 4 + wc] = sm0;
                reds[r1 * 4 + wc] = sm1;
            }
        }
        __syncthreads();

        // ---- update l ----
        #pragma unroll
        for (int mt = 0; mt < 2; mt++) {
            int r0 = wr * 32 + mt * 16 + rowt;
            int r1 = r0 + 8;
            lrow[mt*2]   = lrow[mt*2]   * crr[mt*2]
                         + reds[r0*4] + reds[r0*4+1] + reds[r0*4+2] + reds[r0*4+3];
            lrow[mt*2+1] = lrow[mt*2+1] * crr[mt*2+1]
                         + reds[r1*4] + reds[r1*4+1] + reds[r1*4+2] + reds[r1*4+3];
        }

        // ---- acc += Ph * (Vh + Vl) ----
        #pragma unroll 1
        for (int c = 0; c < 8; c++) {
            const int co = c * 8;
            uint32_t ah[2][4];
            #pragma unroll
            for (int mt = 0; mt < 2; mt++) {
                int o0 = (wr * 32 + mt * 16 + rowt) * AQ_S + co + colt;
                int o1 = o0 + 8 * AQ_S;
                ah[mt][0] = su[U_P + o0];      ah[mt][1] = su[U_P + o1];
                ah[mt][2] = su[U_P + o0 + 4];  ah[mt][3] = su[U_P + o1 + 4];
            }
            #pragma unroll
            for (int nt = 0; nt < 4; nt++) {
                int ob = (co + colt) * AV_S + wc * 32 + nt * 8 + rowt;
                uint32_t bh0 = su[U_KV + ob], bh1 = su[U_KV + ob + 4 * AV_S];
                uint32_t bl0 = su[U_KV + 8704 + ob], bl1 = su[U_KV + 8704 + ob + 4 * AV_S];
                #pragma unroll
                for (int mt = 0; mt < 2; mt++) {
                    mma_f16(acc[mt][nt], ah[mt][0], ah[mt][1], ah[mt][2], ah[mt][3], bh0, bh1);
                    mma_f16(acc[mt][nt], ah[mt][0], ah[mt][1], ah[mt][2], ah[mt][3], bl0, bl1);
                }
            }
        }
    }

    // ---- epilogue ----
    #pragma unroll
    for (int mt = 0; mt < 2; mt++) {
        int r0 = wr * 32 + mt * 16 + rowt;
        float il0 = 1.f / lrow[mt*2];
        float il1 = 1.f / lrow[mt*2+1];
        size_t gr = (size_t)b * S_ + (size_t)qt * 128 + r0;
        #pragma unroll
        for (int nt = 0; nt < 4; nt++) {
            int c0 = wc * 32 + nt * 8 + colt * 2;
            float2 o0 = { acc[mt][nt][0] * il0, acc[mt][nt][1] * il0 };
            float2 o1 = { acc[mt][nt][2] * il1, acc[mt][nt][3] * il1 };
            *(float2*)(out + gr * DK + c0)       = o0;
            *(float2*)(out + (gr + 8) * DK + c0) = o1;
        }
    }
}

// ===================== launch =====================
extern "C" void kernel_launch(void* const* d_in, const int* in_sizes, int n_in,
                              void* d_out, int out_size)
{
    const float* query = (const float*)d_in[0];
    const float* key   = (const float*)d_in[1];
    const float* value = (const float*)d_in[2];
    const int*   maskp = (const int*)  d_in[3];
    const float* Wq    = (const float*)d_in[4];
    const float* Wk    = (const float*)d_in[5];
    const float* Wv    = (const float*)d_in[6];
    float* out = (float*)d_out;

    cudaFuncSetAttribute(proj_mma, cudaFuncAttributeMaxDynamicSharedMemorySize,
                         (int)PJ_SMEM_BYTES);
    cudaFuncSetAttribute(attn_tc, cudaFuncAttributeMaxDynamicSharedMemorySize,
                         (int)A_SMEM_BYTES);

    presplit_w<<<768, 256>>>(Wq, Wk, Wv);
    proj_mma<<<dim3(NROWS / 128, 3), 512, PJ_SMEM_BYTES>>>(query, key, value);
    attn_tc<<<dim3(S_ / 128, B_), 512, A_SMEM_BYTES>>>(maskp, out);
}